// round 6
// baseline (speedup 1.0000x reference)
#include <cuda_runtime.h>

// Problem constants (fixed by the dataset)
#define Bc   2
#define Sc   4096
#define Hc   12
#define Gc   64
#define Wc   513
#define WGc  577      // G + W
#define HALF 256      // W/2
#define BSc  (Bc * Sc)

// Scratch (no device allocation allowed -> __device__ globals)
__device__ float g_local[BSc];       // per (b,i) local sums
__device__ float g_global[Bc * Gc];  // per (b,g) global sums

// ---------------------------------------------------------------------------
// 1) zero scratch (graph-replay deterministic)
// ---------------------------------------------------------------------------
__global__ void init_kernel() {
    int t = blockIdx.x * blockDim.x + threadIdx.x;
    if (t < BSc) g_local[t] = 0.0f;
    if (t < Bc * Gc) g_global[t] = 0.0f;
}

// ---------------------------------------------------------------------------
// 2) local diagonal sums, gather formulation:
//    local_sum[b,i] = sum_{s=i-256..i+256, 0<=s<S} sum_h probs[b,s,h, G+i+256-s]
//    Warp owns 32 consecutive i (lane = i offset) -> coalesced 128B loads.
//    grid: 256 i-tiles * 4 s-splits = 1024 blocks, 256 threads.
// ---------------------------------------------------------------------------
__global__ __launch_bounds__(256) void local_kernel(
    const float* __restrict__ probs, const float* __restrict__ mask)
{
    const int tile  = blockIdx.x >> 2;   // 0..255
    const int split = blockIdx.x & 3;    // 0..3
    const int warp  = threadIdx.x >> 5;  // 0..7
    const int lane  = threadIdx.x & 31;

    const int b  = tile >> 7;            // 128 tiles per batch
    const int i0 = (tile & 127) << 5;    // i base within batch

    // s-window for this i-tile: [i0-256, i0+287], 544 values, 32 chunks of 17
    const int chunk   = split * 8 + warp;
    const int s_start = i0 - HALF + chunk * 17;

    const float* __restrict__ mrow = mask + b * Sc;
    float acc = 0.0f;

    #pragma unroll 1
    for (int t = 0; t < 17; ++t) {
        const int s = s_start + t;
        if (s < 0 || s >= Sc) continue;
        const int c = Gc + HALF + i0 - s + lane;   // column for lane's i
        if (c < Gc || c >= WGc) continue;          // edges of the diagonal band
        const float flag = (mrow[s] >= 0.0f) ? 1.0f : 0.0f;
        const float* __restrict__ row =
            probs + (size_t)(b * Sc + s) * Hc * WGc + c;
        float a = 0.0f;
        #pragma unroll
        for (int h = 0; h < Hc; ++h)               // 12 independent loads (MLP)
            a += row[(size_t)h * WGc];
        acc += flag * a;
    }

    __shared__ float red[8][33];
    red[warp][lane] = acc;
    __syncthreads();
    if (warp == 0) {
        float tot = 0.0f;
        #pragma unroll
        for (int w2 = 0; w2 < 8; ++w2) tot += red[w2][lane];
        atomicAdd(&g_local[b * Sc + i0 + lane], tot);  // 4 blocks per i-tile
    }
}

// ---------------------------------------------------------------------------
// 3) global column sums: global_sum[b,c] = sum_{s,h} probs[b,s,h,c], c<64
//    grid: 2 * 96 blocks, 256 threads = (4 row-groups) x (64 columns)
// ---------------------------------------------------------------------------
__global__ __launch_bounds__(256) void global_kernel(
    const float* __restrict__ probs, const float* __restrict__ mask)
{
    const int b     = blockIdx.x / 96;
    const int chunk = blockIdx.x % 96;
    const int c     = threadIdx.x & 63;
    const int rg    = threadIdx.x >> 6;

    const float* __restrict__ mrow = mask + b * Sc;
    const float* __restrict__ base = probs + (size_t)b * Sc * Hc * WGc;

    float acc = 0.0f;
    const int r0 = chunk * 512;       // rows are (s*H + h), 49152 per batch
    #pragma unroll 8
    for (int r = r0 + rg; r < r0 + 512; r += 4) {
        const int s = r / Hc;
        const float flag = (mrow[s] >= 0.0f) ? 1.0f : 0.0f;
        acc += flag * base[(size_t)r * WGc + c];
    }

    __shared__ float red[4][64];
    red[rg][c] = acc;
    __syncthreads();
    if (rg == 0) {
        float tot = red[0][c] + red[1][c] + red[2][c] + red[3][c];
        atomicAdd(&g_global[b * Gc + c], tot);
    }
}

// ---------------------------------------------------------------------------
// 4) scatter: probs_sum[loc_b,loc_i] += global_sum[glob_b,glob_i]
//    Index dtype may be int64 (x64 jax) or int32 (default jax downcast).
//    Detect on-device from glob_i: int32 data read as 8-byte words produces
//    values >= 2^32 (high half nonzero). Scan only n/2 words (safe in both
//    layouts: n/2 * 8 bytes <= real buffer size either way).
// ---------------------------------------------------------------------------
__global__ void scatter_kernel(const void* __restrict__ lbv,
                               const void* __restrict__ liv,
                               const void* __restrict__ gbv,
                               const void* __restrict__ giv, int n)
{
    __shared__ int is32;
    if (threadIdx.x == 0) {
        int f = 0;
        const long long* gi64 = (const long long*)giv;
        for (int k = 0; k < n / 2; ++k) {
            long long v = gi64[k];
            if (v < 0 || v >= (1LL << 31)) f = 1;
        }
        is32 = f;
    }
    __syncthreads();

    const int k = threadIdx.x + blockIdx.x * blockDim.x;
    if (k < n) {
        int lb, li, gb, gi;
        if (is32) {
            lb = ((const int*)lbv)[k];
            li = ((const int*)liv)[k];
            gb = ((const int*)gbv)[k];
            gi = ((const int*)giv)[k];
        } else {
            lb = (int)((const long long*)lbv)[k];
            li = (int)((const long long*)liv)[k];
            gb = (int)((const long long*)gbv)[k];
            gi = (int)((const long long*)giv)[k];
        }
        atomicAdd(&g_local[lb * Sc + li], g_global[gb * Gc + gi]);
    }
}

// ---------------------------------------------------------------------------
// 5) finalize: per-batch max, scores = sum/max, mask = (score<thr ? -1e4 : 0)
//    Output layout: [ new_attention_mask (B*S) | scores (B*S) ]
// ---------------------------------------------------------------------------
__global__ __launch_bounds__(256) void finalize_kernel(
    const float* __restrict__ thr_p, float* __restrict__ out)
{
    const int b   = blockIdx.x;
    const int tid = threadIdx.x;

    float v[16];
    float m = -1e30f;
    #pragma unroll
    for (int k = 0; k < 16; ++k) {
        v[k] = g_local[b * Sc + tid * 16 + k];
        m = fmaxf(m, v[k]);
    }

    __shared__ float sm[256];
    sm[tid] = m;
    __syncthreads();
    for (int off = 128; off >= 1; off >>= 1) {
        if (tid < off) sm[tid] = fmaxf(sm[tid], sm[tid + off]);
        __syncthreads();
    }
    const float pm  = sm[0];
    const float thr = fmaxf(1e-5f, thr_p[0]);

    #pragma unroll
    for (int k = 0; k < 16; ++k) {
        const int i = tid * 16 + k;
        const float sc = v[k] / pm;
        out[b * Sc + i]       = (sc < thr) ? -10000.0f : 0.0f;  // new mask
        out[BSc + b * Sc + i] = sc;                             // scores
    }
}

// ---------------------------------------------------------------------------
// launch — graph-capturable, allocation-free
// Inputs (metadata order): attention_mask f32[8192], attention_probs
// f32[56696832], keep_threshold f32[1], max_num_global_attn_indices (unused),
// loc_b, loc_i, glob_b, glob_i (index arrays, 128 each).
// ---------------------------------------------------------------------------
extern "C" void kernel_launch(void* const* d_in, const int* in_sizes, int n_in,
                              void* d_out, int out_size)
{
    const float* mask  = (const float*)d_in[0];
    const float* probs = (const float*)d_in[1];
    const float* thr   = (const float*)d_in[2];
    const void*  lb    = d_in[4];
    const void*  li    = d_in[5];
    const void*  gb    = d_in[6];
    const void*  gi    = d_in[7];
    float* out = (float*)d_out;
    const int n_idx = in_sizes[4];

    init_kernel<<<(BSc + 255) / 256, 256>>>();
    local_kernel<<<(BSc / 32) * 4, 256>>>(probs, mask);   // 1024 blocks
    global_kernel<<<Bc * 96, 256>>>(probs, mask);         // 192 blocks
    scatter_kernel<<<1, 128>>>(lb, li, gb, gi, n_idx);
    finalize_kernel<<<Bc, 256>>>(thr, out);
}

// round 7
// speedup vs baseline: 1.2969x; 1.2969x over previous
#include <cuda_runtime.h>

// Problem constants (fixed by the dataset)
#define Bc   2
#define Sc   4096
#define Hc   12
#define Gc   64
#define Wc   513
#define WGc  577      // G + W
#define HALF 256      // W/2
#define BSc  (Bc * Sc)

#define N_LOCAL_BLOCKS  1024   // 256 i-tiles * 4 s-splits
#define N_GCHUNK        96     // row-chunks per batch for global sums
#define N_GLOBAL_BLOCKS (Bc * N_GCHUNK)

// Scratch (plain stores only -> no init kernel, replay-deterministic)
__device__ float g_local_part[4 * BSc];                    // per-split local partials
__device__ float g_glob_part[N_GLOBAL_BLOCKS * Gc];        // per-chunk global partials

// ---------------------------------------------------------------------------
// Fused main pass: reads all 227 MB of probs exactly once, coalesced.
//
// Local role (blocks 0..1023), gather formulation:
//   local_sum[b,i] = sum_{s=i-256..i+256} sum_h probs[b,s,h, 320+i-s]
//   Warp owns 32 consecutive i (lane = i offset) -> contiguous 128B loads.
// Global role (blocks 1024..1215):
//   global_sum[b,c] = sum_{s,h} probs[b,s,h,c], c < 64
// ---------------------------------------------------------------------------
__global__ __launch_bounds__(256) void main_kernel(
    const float* __restrict__ probs, const float* __restrict__ mask)
{
    if (blockIdx.x < N_LOCAL_BLOCKS) {
        const int tile  = blockIdx.x >> 2;   // 0..255
        const int split = blockIdx.x & 3;    // 0..3
        const int warp  = threadIdx.x >> 5;  // 0..7
        const int lane  = threadIdx.x & 31;

        const int b  = tile >> 7;            // 128 tiles per batch
        const int i0 = (tile & 127) << 5;    // i base within batch

        // s-window for this i-tile: [i0-256, i0+287], 544 values = 32 x 17
        const int chunk   = split * 8 + warp;
        const int s_start = i0 - HALF + chunk * 17;

        const float* __restrict__ mrow = mask + b * Sc;
        float acc = 0.0f;

        #pragma unroll 1
        for (int t = 0; t < 17; ++t) {
            const int s = s_start + t;
            if (s < 0 || s >= Sc) continue;
            const int c = Gc + HALF + i0 - s + lane;   // column for lane's i
            if (c < Gc || c >= WGc) continue;          // diagonal band edges
            const float flag = (mrow[s] >= 0.0f) ? 1.0f : 0.0f;
            const float* __restrict__ row =
                probs + (size_t)(b * Sc + s) * Hc * WGc + c;
            float a = 0.0f;
            #pragma unroll
            for (int h = 0; h < Hc; ++h)               // 12 independent loads
                a += row[(size_t)h * WGc];
            acc += flag * a;
        }

        __shared__ float red[8][33];
        red[warp][lane] = acc;
        __syncthreads();
        if (warp == 0) {
            float tot = 0.0f;
            #pragma unroll
            for (int w2 = 0; w2 < 8; ++w2) tot += red[w2][lane];
            g_local_part[split * BSc + b * Sc + i0 + lane] = tot;  // plain store
        }
    } else {
        const int idx   = blockIdx.x - N_LOCAL_BLOCKS;   // 0..191
        const int b     = idx / N_GCHUNK;
        const int chunk = idx % N_GCHUNK;
        const int c     = threadIdx.x & 63;
        const int rg    = threadIdx.x >> 6;

        const float* __restrict__ mrow = mask + b * Sc;
        const float* __restrict__ base = probs + (size_t)b * Sc * Hc * WGc;

        float acc = 0.0f;
        const int r0 = chunk * 512;      // rows are (s*H + h), 49152 per batch
        #pragma unroll 8
        for (int r = r0 + rg; r < r0 + 512; r += 4) {
            const int s = r / Hc;
            const float flag = (mrow[s] >= 0.0f) ? 1.0f : 0.0f;
            acc += flag * base[(size_t)r * WGc + c];
        }

        __shared__ float gred[4][64];
        gred[rg][c] = acc;
        __syncthreads();
        if (rg == 0)
            g_glob_part[idx * Gc + c] =
                gred[0][c] + gred[1][c] + gred[2][c] + gred[3][c];
    }
}

// ---------------------------------------------------------------------------
// Fused finalize: partial-sum + global-sum + scatter + max + threshold.
// One block per batch, 256 threads.
// ---------------------------------------------------------------------------
__global__ __launch_bounds__(256) void finalize_kernel(
    const float* __restrict__ thr_p,
    const void* __restrict__ lbv, const void* __restrict__ liv,
    const void* __restrict__ gbv, const void* __restrict__ giv,
    int n, float* __restrict__ out)
{
    __shared__ float ps[Sc];        // probs_sum for this batch (16 KB)
    __shared__ float gs[Bc * Gc];   // global sums, BOTH batches (cross-b scatter)
    __shared__ float sm[256];
    __shared__ int   is32;

    const int b   = blockIdx.x;
    const int tid = threadIdx.x;

    // 1) sum the 4 local partials -> smem
    #pragma unroll
    for (int k = 0; k < 16; ++k) {
        const int i = tid * 16 + k;
        ps[i] = g_local_part[0 * BSc + b * Sc + i]
              + g_local_part[1 * BSc + b * Sc + i]
              + g_local_part[2 * BSc + b * Sc + i]
              + g_local_part[3 * BSc + b * Sc + i];
    }

    // 2) sum global partials for both batches (128 outputs)
    if (tid < Bc * Gc) {
        const int bb = tid >> 6, c = tid & 63;
        float a = 0.0f;
        #pragma unroll 8
        for (int ch = 0; ch < N_GCHUNK; ++ch)
            a += g_glob_part[(bb * N_GCHUNK + ch) * Gc + c];
        gs[tid] = a;
    }

    if (tid == 0) is32 = 0;
    __syncthreads();

    // 3) parallel dtype detect on glob_i: int32 data viewed as int64 words
    //    yields values outside [0, 2^31). Scan n/2 words (safe either layout).
    if (tid < n / 2) {
        const long long v = ((const long long*)giv)[tid];
        if (v < 0 || v >= (1LL << 31)) atomicOr(&is32, 1);
    }
    __syncthreads();

    // 4) scatter: probs_sum[lb, li] += global_sum[gb, gi]  (duplicates add)
    if (tid < n) {
        int lb, li, gb, gi;
        if (is32) {
            lb = ((const int*)lbv)[tid];
            li = ((const int*)liv)[tid];
            gb = ((const int*)gbv)[tid];
            gi = ((const int*)giv)[tid];
        } else {
            lb = (int)((const long long*)lbv)[tid];
            li = (int)((const long long*)liv)[tid];
            gb = (int)((const long long*)gbv)[tid];
            gi = (int)((const long long*)giv)[tid];
        }
        if (lb == b) atomicAdd(&ps[li], gs[gb * Gc + gi]);
    }
    __syncthreads();

    // 5) per-batch max
    float v[16], m = -1e30f;
    #pragma unroll
    for (int k = 0; k < 16; ++k) {
        v[k] = ps[tid * 16 + k];
        m = fmaxf(m, v[k]);
    }
    sm[tid] = m;
    __syncthreads();
    for (int off = 128; off >= 1; off >>= 1) {
        if (tid < off) sm[tid] = fmaxf(sm[tid], sm[tid + off]);
        __syncthreads();
    }
    const float pm  = sm[0];
    const float thr = fmaxf(1e-5f, thr_p[0]);

    // 6) outputs: [ new_attention_mask (B*S) | scores (B*S) ]
    #pragma unroll
    for (int k = 0; k < 16; ++k) {
        const int i = tid * 16 + k;
        const float sc = v[k] / pm;
        out[b * Sc + i]       = (sc < thr) ? -10000.0f : 0.0f;
        out[BSc + b * Sc + i] = sc;
    }
}

// ---------------------------------------------------------------------------
// launch — 2 graph nodes, allocation-free.
// Inputs (metadata order): attention_mask f32, attention_probs f32,
// keep_threshold f32[1], max_num_global_attn_indices (unused),
// loc_b, loc_i, glob_b, glob_i.
// ---------------------------------------------------------------------------
extern "C" void kernel_launch(void* const* d_in, const int* in_sizes, int n_in,
                              void* d_out, int out_size)
{
    const float* mask  = (const float*)d_in[0];
    const float* probs = (const float*)d_in[1];
    const float* thr   = (const float*)d_in[2];
    const void*  lb    = d_in[4];
    const void*  li    = d_in[5];
    const void*  gb    = d_in[6];
    const void*  gi    = d_in[7];
    float* out = (float*)d_out;
    const int n_idx = in_sizes[4];

    main_kernel<<<N_LOCAL_BLOCKS + N_GLOBAL_BLOCKS, 256>>>(probs, mask);
    finalize_kernel<<<Bc, 256>>>(thr, lb, li, gb, gi, n_idx, out);
}